// round 6
// baseline (speedup 1.0000x reference)
#include <cuda_runtime.h>
#include <cstdint>

#define B_SZ    8192
#define IN_DIMS 784
#define NETS    30
#define NODES   20
#define OUTC    10
#define DIMK    16
#define H1C     (NETS * NODES)   // 600

typedef unsigned long long ull;

// ---------------- scratch (device globals; no allocations) ----------------
__device__ float g_W1p[IN_DIMS * H1C];              // packed W1 [i][n*20+o]
__device__ float g_h1[(size_t)B_SZ * H1C];
__device__ float g_u [(size_t)B_SZ * H1C];

// ---------------- f32x2 helpers (Blackwell packed fp32) --------------------
__device__ __forceinline__ ull pack2(float lo, float hi) {
    ull r;
    asm("mov.b64 %0, {%1, %2};" : "=l"(r) : "f"(lo), "f"(hi));
    return r;
}
__device__ __forceinline__ void fma2(ull& d, ull a, ull b) {
    asm("fma.rn.f32x2 %0, %1, %2, %0;" : "+l"(d) : "l"(a), "l"(b));
}
__device__ __forceinline__ void unpack2(ull v, float& lo, float& hi) {
    asm("mov.b64 {%0, %1}, %2;" : "=f"(lo), "=f"(hi) : "l"(v));
}

// ---------------- kernel 0: pack W1 [n][i][o] -> [i][n*20+o] ---------------
__global__ void k_pack(const float* __restrict__ W1) {
    int total = IN_DIMS * H1C;
    for (int i = blockIdx.x * blockDim.x + threadIdx.x; i < total;
         i += gridDim.x * blockDim.x) {
        int row = i / H1C;
        int col = i - row * H1C;
        int n = col / NODES, o = col - n * NODES;
        g_W1p[i] = W1[(n * IN_DIMS + row) * NODES + o];
    }
}

// ---------------- kernel 1: h1 = relu(x @ W1p + b1) ------------------------
// A duplicated in smem as float2(a,a) so fma2 operands come straight from LDS.
#define BM 128
#define BN 128
#define BK 8

__global__ __launch_bounds__(256, 2)
void k_gemm1(const float* __restrict__ X, const float* __restrict__ b1) {
    __shared__ float2 As2[2][BK][BM];   // 16 KB (duplicated A)
    __shared__ float  Bs [2][BK][BN];   // 8 KB

    const int tid  = threadIdx.x;
    const int tx   = tid & 15;
    const int ty   = tid >> 4;
    const int m0   = blockIdx.y * BM;
    const int col0 = blockIdx.x * BN;

    const int a_row = tid >> 1;
    const int a_c4  = (tid & 1) * 4;
    const int b_r   = tid >> 5;
    const int b_c4  = (tid & 31) * 4;
    const int bcol  = col0 + b_c4;
    const bool bvalid = (bcol < H1C);

    // stage 0
    {
        float4 av = *(const float4*)(X + (size_t)(m0 + a_row) * IN_DIMS + a_c4);
        As2[0][a_c4 + 0][a_row] = make_float2(av.x, av.x);
        As2[0][a_c4 + 1][a_row] = make_float2(av.y, av.y);
        As2[0][a_c4 + 2][a_row] = make_float2(av.z, av.z);
        As2[0][a_c4 + 3][a_row] = make_float2(av.w, av.w);
        float4 bv = bvalid ? *(const float4*)(g_W1p + (size_t)b_r * H1C + bcol)
                           : make_float4(0.f, 0.f, 0.f, 0.f);
        *(float4*)&Bs[0][b_r][b_c4] = bv;
    }
    __syncthreads();

    ull acc[8][4];
#pragma unroll
    for (int i = 0; i < 8; i++)
#pragma unroll
        for (int j = 0; j < 4; j++) acc[i][j] = 0ull;

    int buf = 0;
    for (int kt = 0; kt < IN_DIMS; kt += BK) {
        float4 aP, bP;
        const bool more = (kt + BK) < IN_DIMS;
        if (more) {
            aP = *(const float4*)(X + (size_t)(m0 + a_row) * IN_DIMS + kt + BK + a_c4);
            bP = bvalid ? *(const float4*)(g_W1p + (size_t)(kt + BK + b_r) * H1C + bcol)
                        : make_float4(0.f, 0.f, 0.f, 0.f);
        }
#pragma unroll
        for (int kk = 0; kk < BK; kk++) {
            ull a8[8];
#pragma unroll
            for (int i = 0; i < 8; i++)
                a8[i] = *(const ull*)&As2[buf][kk][ty * 8 + i];
            ulonglong2 q0 = *(const ulonglong2*)&Bs[buf][kk][tx * 8];
            ulonglong2 q1 = *(const ulonglong2*)&Bs[buf][kk][tx * 8 + 4];
#pragma unroll
            for (int i = 0; i < 8; i++) {
                fma2(acc[i][0], a8[i], q0.x);
                fma2(acc[i][1], a8[i], q0.y);
                fma2(acc[i][2], a8[i], q1.x);
                fma2(acc[i][3], a8[i], q1.y);
            }
        }
        if (more) {
            As2[buf ^ 1][a_c4 + 0][a_row] = make_float2(aP.x, aP.x);
            As2[buf ^ 1][a_c4 + 1][a_row] = make_float2(aP.y, aP.y);
            As2[buf ^ 1][a_c4 + 2][a_row] = make_float2(aP.z, aP.z);
            As2[buf ^ 1][a_c4 + 3][a_row] = make_float2(aP.w, aP.w);
            *(float4*)&Bs[buf ^ 1][b_r][b_c4] = bP;
            __syncthreads();
            buf ^= 1;
        }
    }

    const int c0 = col0 + tx * 8;
    const bool cvalid = (c0 < H1C);
    float bias[8];
    if (cvalid) {
#pragma unroll
        for (int j = 0; j < 8; j++) bias[j] = __ldg(b1 + c0 + j);
    }
#pragma unroll
    for (int i = 0; i < 8; i++) {
        int row = m0 + ty * 8 + i;
        float c[8];
        unpack2(acc[i][0], c[0], c[1]);
        unpack2(acc[i][1], c[2], c[3]);
        unpack2(acc[i][2], c[4], c[5]);
        unpack2(acc[i][3], c[6], c[7]);
        if (cvalid) {
#pragma unroll
            for (int j = 0; j < 8; j++) c[j] = fmaxf(c[j] + bias[j], 0.f);
            float* dst = g_h1 + (size_t)row * H1C + c0;
            *(float4*)dst       = make_float4(c[0], c[1], c[2], c[3]);
            *(float4*)(dst + 4) = make_float4(c[4], c[5], c[6], c[7]);
        }
    }
}

// ---------------- kernel 2: h2 = relu(h1@W2+b2); u = squash(h2) -----------
__global__ __launch_bounds__(256)
void k_h2u(const float* __restrict__ W2, const float* __restrict__ b2) {
    extern __shared__ float sh[];
    float* W2s = sh;
    float* b2s = sh + NETS * NODES * NODES;

    for (int i = threadIdx.x; i < NETS * NODES * NODES; i += blockDim.x)
        W2s[i] = W2[i];
    for (int i = threadIdx.x; i < NETS * NODES; i += blockDim.x)
        b2s[i] = b2[i];
    __syncthreads();

    const int lane  = threadIdx.x & 31;
    const int warp  = threadIdx.x >> 5;
    const int gw    = blockIdx.x * (blockDim.x >> 5) + warp;
    const int nwarp = gridDim.x * (blockDim.x >> 5);
    const int e     = (lane < NODES) ? lane : 0;
    const bool act  = lane < NODES;

    for (int t = gw; t < B_SZ * NETS; t += nwarp) {
        int b = t / NETS, n = t - b * NETS;
        float acc = act ? b2s[n * NODES + e] : 0.f;
        const float4* h4 = (const float4*)(g_h1 + (size_t)b * H1C + n * NODES);
        float hv[NODES];
#pragma unroll
        for (int q = 0; q < NODES / 4; q++) {
            float4 v = __ldg(h4 + q);
            hv[q * 4 + 0] = v.x; hv[q * 4 + 1] = v.y;
            hv[q * 4 + 2] = v.z; hv[q * 4 + 3] = v.w;
        }
#pragma unroll
        for (int d = 0; d < NODES; d++)
            acc = fmaf(hv[d], W2s[(n * NODES + d) * NODES + e], acc);
        float h = act ? fmaxf(acc, 0.f) : 0.f;
        float sq = h * h;
#pragma unroll
        for (int off = 16; off > 0; off >>= 1)
            sq += __shfl_xor_sync(0xffffffffu, sq, off);
        float scale = (sq / (1.f + sq)) * rsqrtf(sq);
        if (act)
            g_u[(size_t)b * H1C + n * NODES + e] = h * scale;
    }
}

// ---------------- kernel 3: priors + routing -------------------------------
// TB=8 rows/CTA, 20 warps: warp (o, wsub). Priors: warp covers n-subset for
// ALL 8 rows (RW reuse x8), u pre-paired (b, b+4) in smem for f32x2 via LDS.128.
// Routing: warp (o, wsub) owns rows wsub*4..+3.
#define TB 8
#define RTHREADS 640   // 20 warps

__global__ __launch_bounds__(RTHREADS, 1)
void k_route(const float* __restrict__ RW, float* __restrict__ out) {
    extern __shared__ float sh[];
    float2* u2_s   = (float2*)sh;                          // 4*600 float2 = 19.2KB
    float*  p_s    = sh + 2 * 4 * H1C;                     // 8*4800 = 153.6KB
    float*  logit_s= p_s + TB * OUTC * NETS * DIMK;        // 8*300
    float*  prob_s = logit_s + TB * OUTC * NETS;           // 8*300

    const int tid  = threadIdx.x;
    const int w    = tid >> 5;
    const int o    = w >> 1;
    const int wsub = w & 1;
    const int lane = tid & 31;
    const int k    = lane & 15;
    const int half = lane >> 4;
    const int b0   = blockIdx.x * TB;

    // load u pre-paired: u2_s[b][r] = (u[b0+b][r], u[b0+b+4][r]), b in 0..3
    for (int i = tid; i < 4 * H1C; i += RTHREADS) {
        int b = i / H1C;
        int r = i - b * H1C;
        float lo = g_u[(size_t)(b0 + b) * H1C + r];
        float hi = g_u[(size_t)(b0 + b + 4) * H1C + r];
        u2_s[i] = make_float2(lo, hi);
    }
    __syncthreads();

    // ---- priors: warp (o,wsub) handles n = 4*ni + 2*wsub + half, all 8 rows
#pragma unroll 1
    for (int ni = 0; ni < 8; ni++) {
        const int nbase = 4 * ni + 2 * wsub;      // uniform per warp
        if (nbase >= NETS) continue;
        const int n = nbase + half;
        const float* rw = RW + ((size_t)(o * NETS + n) * NODES) * DIMK + k;
        ull rwp[NODES];
#pragma unroll
        for (int d = 0; d < NODES; d++) {
            float r = __ldg(rw + d * DIMK);
            rwp[d] = pack2(r, r);
        }
        const int pidx = o * (NETS * DIMK) + n * DIMK + k;
#pragma unroll
        for (int bp = 0; bp < 4; bp++) {
            const ull* up = (const ull*)(u2_s + bp * H1C + n * NODES);
            ull acc = 0ull;
#pragma unroll
            for (int d = 0; d < NODES; d += 2) {
                ulonglong2 uu = *(const ulonglong2*)(up + d);
                fma2(acc, uu.x, rwp[d]);
                fma2(acc, uu.y, rwp[d + 1]);
            }
            float plo, phi;
            unpack2(acc, plo, phi);
            p_s[bp * (OUTC * NETS * DIMK) + pidx]       = plo;
            p_s[(bp + 4) * (OUTC * NETS * DIMK) + pidx] = phi;
        }
    }
    __syncthreads();

    // ---- routing: warp (o,wsub) owns rows b = wsub*4 + j
    float v[4];
#pragma unroll 1
    for (int it = 0; it < 3; it++) {
#pragma unroll
        for (int j = 0; j < 4; j++) {
            const int b = wsub * 4 + j;
            const float* pb  = p_s + b * (OUTC * NETS * DIMK) + o * (NETS * DIMK) + k;
            const float* prb = prob_s + b * (OUTC * NETS) + o * NETS;
            float s = 0.f;
            if (it == 0) {
#pragma unroll
                for (int ni = 0; ni < NETS / 2; ni++)
                    s += pb[(2 * ni + half) * DIMK];
                s *= 0.1f;
            } else {
#pragma unroll
                for (int ni = 0; ni < NETS / 2; ni++) {
                    const int n = 2 * ni + half;
                    s = fmaf(prb[n], pb[n * DIMK], s);
                }
            }
            s += __shfl_xor_sync(0xffffffffu, s, 16);
            float sq = s * s;
            sq += __shfl_xor_sync(0xffffffffu, sq, 1);
            sq += __shfl_xor_sync(0xffffffffu, sq, 2);
            sq += __shfl_xor_sync(0xffffffffu, sq, 4);
            sq += __shfl_xor_sync(0xffffffffu, sq, 8);
            v[j] = s * (sq / (1.f + sq)) * rsqrtf(sq);
        }

        if (it < 2) {
#pragma unroll
            for (int j = 0; j < 4; j++) {
                const int b = wsub * 4 + j;
                const float* pb = p_s + b * (OUTC * NETS * DIMK) + o * (NETS * DIMK) + k;
                float* lg = logit_s + b * (OUTC * NETS) + o * NETS;
#pragma unroll
                for (int ni = 0; ni < NETS / 2; ni++) {
                    const int n = 2 * ni + half;
                    float t = pb[n * DIMK] * v[j];
                    t += __shfl_xor_sync(0xffffffffu, t, 1);
                    t += __shfl_xor_sync(0xffffffffu, t, 2);
                    t += __shfl_xor_sync(0xffffffffu, t, 4);
                    t += __shfl_xor_sync(0xffffffffu, t, 8);
                    if (k == 0) lg[n] = (it == 0) ? t : (lg[n] + t);
                }
            }
            __syncthreads();
            // softmax over o per (b, n)
            for (int t = tid; t < TB * NETS; t += RTHREADS) {
                const int b = t / NETS, n = t - b * NETS;
                const float* lg = logit_s + b * (OUTC * NETS) + n;
                float m = -1e30f;
#pragma unroll
                for (int oo = 0; oo < OUTC; oo++)
                    m = fmaxf(m, lg[oo * NETS]);
                float e[OUTC], ssum = 0.f;
#pragma unroll
                for (int oo = 0; oo < OUTC; oo++) {
                    e[oo] = __expf(lg[oo * NETS] - m);
                    ssum += e[oo];
                }
                float inv = 1.f / ssum;
                float* pr = prob_s + b * (OUTC * NETS) + n;
#pragma unroll
                for (int oo = 0; oo < OUTC; oo++)
                    pr[oo * NETS] = e[oo] * inv;
            }
            __syncthreads();
        }
    }

    // output [B,10,16]
    if (half == 0) {
#pragma unroll
        for (int j = 0; j < 4; j++)
            out[((size_t)(b0 + wsub * 4 + j) * OUTC + o) * DIMK + k] = v[j];
    }
}

// ---------------- launcher -------------------------------------------------
extern "C" void kernel_launch(void* const* d_in, const int* in_sizes, int n_in,
                              void* d_out, int out_size) {
    const float* x  = (const float*)d_in[0];
    const float* W1 = (const float*)d_in[1];
    const float* b1 = (const float*)d_in[2];
    const float* W2 = (const float*)d_in[3];
    const float* b2 = (const float*)d_in[4];
    const float* RW = (const float*)d_in[5];
    float* out = (float*)d_out;

    static const size_t smem_h2u   = (size_t)(NETS * NODES * NODES + NETS * NODES) * 4;
    static const size_t smem_route = (size_t)(2 * 4 * H1C +                 // u2 pairs
                                              TB * OUTC * NETS * DIMK +     // priors
                                              2 * TB * OUTC * NETS) * 4;    // logit+prob
    cudaFuncSetAttribute(k_h2u,   cudaFuncAttributeMaxDynamicSharedMemorySize, (int)smem_h2u);
    cudaFuncSetAttribute(k_route, cudaFuncAttributeMaxDynamicSharedMemorySize, (int)smem_route);

    k_pack<<<512, 256>>>(W1);
    dim3 g1((H1C + BN - 1) / BN, B_SZ / BM);
    k_gemm1<<<g1, 256>>>(x, b1);
    k_h2u<<<1024, 256, smem_h2u>>>(W2, b2);
    k_route<<<B_SZ / TB, RTHREADS, smem_route>>>(RW, out);
}

// round 7
// speedup vs baseline: 1.5556x; 1.5556x over previous
#include <cuda_runtime.h>
#include <cuda_bf16.h>
#include <cstdint>

#define B_SZ    8192
#define IN_DIMS 784
#define NETS    30
#define NODES   20
#define OUTC    10
#define DIMK    16
#define H1C     (NETS * NODES)   // 600
#define KPAD    800              // 784 padded to 32-multiple
#define NPAD    640              // 600 padded to 64-multiple

typedef unsigned long long ull;

// ---------------- scratch (device globals; no allocations) ----------------
__device__ __nv_bfloat16 g_Xh[(size_t)B_SZ * KPAD];
__device__ __nv_bfloat16 g_Xl[(size_t)B_SZ * KPAD];
__device__ __nv_bfloat16 g_Wh[(size_t)NPAD * KPAD];   // [col(n-major)][k]
__device__ __nv_bfloat16 g_Wl[(size_t)NPAD * KPAD];
__device__ float g_h1[(size_t)B_SZ * H1C];
__device__ float g_u [(size_t)B_SZ * H1C];

// ---------------- f32x2 helpers -------------------------------------------
__device__ __forceinline__ ull pack2(float lo, float hi) {
    ull r;
    asm("mov.b64 %0, {%1, %2};" : "=l"(r) : "f"(lo), "f"(hi));
    return r;
}
__device__ __forceinline__ void fma2(ull& d, ull a, ull b) {
    asm("fma.rn.f32x2 %0, %1, %2, %0;" : "+l"(d) : "l"(a), "l"(b));
}
__device__ __forceinline__ void unpack2(ull v, float& lo, float& hi) {
    asm("mov.b64 {%0, %1}, %2;" : "=f"(lo), "=f"(hi) : "l"(v));
}

// ---------------- tensor-core helpers --------------------------------------
__device__ __forceinline__ uint32_t s2u(const void* p) {
    return (uint32_t)__cvta_generic_to_shared(p);
}
__device__ __forceinline__ void ldsm4(uint32_t* r, const void* p) {
    uint32_t a = s2u(p);
    asm volatile("ldmatrix.sync.aligned.m8n8.x4.shared.b16 {%0,%1,%2,%3}, [%4];"
                 : "=r"(r[0]), "=r"(r[1]), "=r"(r[2]), "=r"(r[3]) : "r"(a));
}
__device__ __forceinline__ void mma_bf16(float* d, const uint32_t* a, const uint32_t* b) {
    asm volatile("mma.sync.aligned.m16n8k16.row.col.f32.bf16.bf16.f32 "
                 "{%0,%1,%2,%3},{%4,%5,%6,%7},{%8,%9},{%0,%1,%2,%3};"
                 : "+f"(d[0]), "+f"(d[1]), "+f"(d[2]), "+f"(d[3])
                 : "r"(a[0]), "r"(a[1]), "r"(a[2]), "r"(a[3]),
                   "r"(b[0]), "r"(b[1]));
}

// ---------------- kernel 0a: X f32 -> (Xh, Xl) bf16, K padded --------------
__global__ void k_convA(const float* __restrict__ X) {
    const size_t total = (size_t)B_SZ * KPAD;
    for (size_t i = (size_t)blockIdx.x * blockDim.x + threadIdx.x; i < total;
         i += (size_t)gridDim.x * blockDim.x) {
        int row = (int)(i / KPAD);
        int c   = (int)(i - (size_t)row * KPAD);
        float v = (c < IN_DIMS) ? X[(size_t)row * IN_DIMS + c] : 0.f;
        __nv_bfloat16 hi = __float2bfloat16_rn(v);
        __nv_bfloat16 lo = __float2bfloat16_rn(v - __bfloat162float(hi));
        g_Xh[i] = hi;
        g_Xl[i] = lo;
    }
}

// ---------------- kernel 0b: W1 [n][i][o] -> (Wh, Wl) [col][k] padded ------
__global__ void k_convW(const float* __restrict__ W1) {
    const int total = NPAD * KPAD;
    for (int i = blockIdx.x * blockDim.x + threadIdx.x; i < total;
         i += gridDim.x * blockDim.x) {
        int col = i / KPAD;
        int kk  = i - col * KPAD;
        float v = 0.f;
        if (col < H1C && kk < IN_DIMS) {
            int net = col / NODES, o = col - net * NODES;
            v = W1[((size_t)net * IN_DIMS + kk) * NODES + o];
        }
        __nv_bfloat16 hi = __float2bfloat16_rn(v);
        __nv_bfloat16 lo = __float2bfloat16_rn(v - __bfloat162float(hi));
        g_Wh[i] = hi;
        g_Wl[i] = lo;
    }
}

// ---------------- kernel 1: h1 = relu(x @ W1 + b1) via bf16 split mma ------
// CTA tile 128x64, BK=32, 8 warps (4M x 2N), warp tile 32x32.
#define GBM 128
#define GBN 64
#define GBK 32
#define SROW 40   // smem row stride in bf16 (32 data + 8 pad => 80B)

__global__ __launch_bounds__(256, 2)
void k_gemm_tc(const float* __restrict__ b1) {
    __shared__ __align__(16) __nv_bfloat16 Ah_s[GBM][SROW];
    __shared__ __align__(16) __nv_bfloat16 Al_s[GBM][SROW];
    __shared__ __align__(16) __nv_bfloat16 Bh_s[GBN][SROW];
    __shared__ __align__(16) __nv_bfloat16 Bl_s[GBN][SROW];

    const int tid  = threadIdx.x;
    const int lane = tid & 31;
    const int w    = tid >> 5;
    const int wm   = (w & 3) * 32;
    const int wn   = (w >> 2) * 32;
    const int m0   = blockIdx.y * GBM;
    const int n0   = blockIdx.x * GBN;

    // gmem<->smem chunk mapping (16B chunks of 8 bf16)
    const int ar0 = (tid)       >> 2, as0 = (tid)       & 3;       // A chunk t=0
    const int ar1 = (tid + 256) >> 2, as1 = (tid + 256) & 3;       // A chunk t=1
    const int br  = tid >> 2,        bs  = tid & 3;                // B chunk

    float acc[2][4][4];
#pragma unroll
    for (int i = 0; i < 2; i++)
#pragma unroll
        for (int j = 0; j < 4; j++)
#pragma unroll
            for (int q = 0; q < 4; q++) acc[i][j][q] = 0.f;

    uint4 pa0, pa1, pl0, pl1, pb, pbl;
    // prologue: stage 0
    {
        const size_t ka0 = (size_t)(m0 + ar0) * KPAD + as0 * 8;
        const size_t ka1 = (size_t)(m0 + ar1) * KPAD + as1 * 8;
        const size_t kb  = (size_t)(n0 + br)  * KPAD + bs  * 8;
        pa0 = *(const uint4*)(g_Xh + ka0);  pl0 = *(const uint4*)(g_Xl + ka0);
        pa1 = *(const uint4*)(g_Xh + ka1);  pl1 = *(const uint4*)(g_Xl + ka1);
        pb  = *(const uint4*)(g_Wh + kb);   pbl = *(const uint4*)(g_Wl + kb);
        *(uint4*)&Ah_s[ar0][as0 * 8] = pa0; *(uint4*)&Al_s[ar0][as0 * 8] = pl0;
        *(uint4*)&Ah_s[ar1][as1 * 8] = pa1; *(uint4*)&Al_s[ar1][as1 * 8] = pl1;
        *(uint4*)&Bh_s[br][bs * 8]   = pb;  *(uint4*)&Bl_s[br][bs * 8]   = pbl;
    }
    __syncthreads();

    // ldmatrix per-lane row/col offsets
    const int a_r   = lane & 15;            // row within m16
    const int a_k8  = (lane >> 4) * 8;      // k-half select
    const int b_r   = ((lane >> 4) & 1) * 8 + (lane & 7);
    const int b_k8  = ((lane >> 3) & 1) * 8;

    const int NSTAGE = KPAD / GBK;          // 25
    for (int s = 0; s < NSTAGE; s++) {
        if (s + 1 < NSTAGE) {
            const int kt = (s + 1) * GBK;
            const size_t ka0 = (size_t)(m0 + ar0) * KPAD + kt + as0 * 8;
            const size_t ka1 = (size_t)(m0 + ar1) * KPAD + kt + as1 * 8;
            const size_t kb  = (size_t)(n0 + br)  * KPAD + kt + bs  * 8;
            pa0 = *(const uint4*)(g_Xh + ka0);  pl0 = *(const uint4*)(g_Xl + ka0);
            pa1 = *(const uint4*)(g_Xh + ka1);  pl1 = *(const uint4*)(g_Xl + ka1);
            pb  = *(const uint4*)(g_Wh + kb);   pbl = *(const uint4*)(g_Wl + kb);
        }
#pragma unroll
        for (int ksub = 0; ksub < 2; ksub++) {
            uint32_t aH[2][4], aL[2][4], bH[2][4], bL[2][4];
#pragma unroll
            for (int mi = 0; mi < 2; mi++) {
                ldsm4(aH[mi], &Ah_s[wm + mi * 16 + a_r][ksub * 16 + a_k8]);
                ldsm4(aL[mi], &Al_s[wm + mi * 16 + a_r][ksub * 16 + a_k8]);
            }
#pragma unroll
            for (int p = 0; p < 2; p++) {
                ldsm4(bH[p], &Bh_s[wn + p * 16 + b_r][ksub * 16 + b_k8]);
                ldsm4(bL[p], &Bl_s[wn + p * 16 + b_r][ksub * 16 + b_k8]);
            }
#pragma unroll
            for (int mi = 0; mi < 2; mi++)
#pragma unroll
                for (int p = 0; p < 2; p++) {
                    mma_bf16(acc[mi][2 * p],     aH[mi], bH[p]);
                    mma_bf16(acc[mi][2 * p + 1], aH[mi], bH[p] + 2);
                    mma_bf16(acc[mi][2 * p],     aH[mi], bL[p]);
                    mma_bf16(acc[mi][2 * p + 1], aH[mi], bL[p] + 2);
                    mma_bf16(acc[mi][2 * p],     aL[mi], bH[p]);
                    mma_bf16(acc[mi][2 * p + 1], aL[mi], bH[p] + 2);
                }
        }
        __syncthreads();
        if (s + 1 < NSTAGE) {
            *(uint4*)&Ah_s[ar0][as0 * 8] = pa0; *(uint4*)&Al_s[ar0][as0 * 8] = pl0;
            *(uint4*)&Ah_s[ar1][as1 * 8] = pa1; *(uint4*)&Al_s[ar1][as1 * 8] = pl1;
            *(uint4*)&Bh_s[br][bs * 8]   = pb;  *(uint4*)&Bl_s[br][bs * 8]   = pbl;
            __syncthreads();
        }
    }

    // epilogue: bias + relu + predicated store
    const int r0 = lane >> 2;
    const int c0 = (lane & 3) * 2;
#pragma unroll
    for (int mi = 0; mi < 2; mi++) {
#pragma unroll
        for (int ni = 0; ni < 4; ni++) {
            const int col = n0 + wn + ni * 8 + c0;
            if (col < H1C) {
                float bb0 = __ldg(b1 + col);
                float bb1 = __ldg(b1 + col + 1);
                const int rowA = m0 + wm + mi * 16 + r0;
                float v0 = fmaxf(acc[mi][ni][0] + bb0, 0.f);
                float v1 = fmaxf(acc[mi][ni][1] + bb1, 0.f);
                *(float2*)(g_h1 + (size_t)rowA * H1C + col) = make_float2(v0, v1);
                float v2 = fmaxf(acc[mi][ni][2] + bb0, 0.f);
                float v3 = fmaxf(acc[mi][ni][3] + bb1, 0.f);
                *(float2*)(g_h1 + (size_t)(rowA + 8) * H1C + col) = make_float2(v2, v3);
            }
        }
    }
}

// ---------------- kernel 2: h2 = relu(h1@W2+b2); u = squash(h2) -----------
__global__ __launch_bounds__(256)
void k_h2u(const float* __restrict__ W2, const float* __restrict__ b2) {
    extern __shared__ float sh[];
    float* W2s = sh;
    float* b2s = sh + NETS * NODES * NODES;

    for (int i = threadIdx.x; i < NETS * NODES * NODES; i += blockDim.x)
        W2s[i] = W2[i];
    for (int i = threadIdx.x; i < NETS * NODES; i += blockDim.x)
        b2s[i] = b2[i];
    __syncthreads();

    const int lane  = threadIdx.x & 31;
    const int warp  = threadIdx.x >> 5;
    const int gw    = blockIdx.x * (blockDim.x >> 5) + warp;
    const int nwarp = gridDim.x * (blockDim.x >> 5);
    const int e     = (lane < NODES) ? lane : 0;
    const bool act  = lane < NODES;

    for (int t = gw; t < B_SZ * NETS; t += nwarp) {
        int b = t / NETS, n = t - b * NETS;
        float acc = act ? b2s[n * NODES + e] : 0.f;
        const float4* h4 = (const float4*)(g_h1 + (size_t)b * H1C + n * NODES);
        float hv[NODES];
#pragma unroll
        for (int q = 0; q < NODES / 4; q++) {
            float4 v = __ldg(h4 + q);
            hv[q * 4 + 0] = v.x; hv[q * 4 + 1] = v.y;
            hv[q * 4 + 2] = v.z; hv[q * 4 + 3] = v.w;
        }
#pragma unroll
        for (int d = 0; d < NODES; d++)
            acc = fmaf(hv[d], W2s[(n * NODES + d) * NODES + e], acc);
        float h = act ? fmaxf(acc, 0.f) : 0.f;
        float sq = h * h;
#pragma unroll
        for (int off = 16; off > 0; off >>= 1)
            sq += __shfl_xor_sync(0xffffffffu, sq, off);
        float scale = (sq / (1.f + sq)) * rsqrtf(sq);
        if (act)
            g_u[(size_t)b * H1C + n * NODES + e] = h * scale;
    }
}

// ---------------- kernel 3: priors + routing (R6 structure, measured) ------
#define TB 8
#define RTHREADS 640   // 20 warps

__global__ __launch_bounds__(RTHREADS, 1)
void k_route(const float* __restrict__ RW, float* __restrict__ out) {
    extern __shared__ float sh[];
    float2* u2_s   = (float2*)sh;                          // 4*600 float2
    float*  p_s    = sh + 2 * 4 * H1C;                     // 8*4800
    float*  logit_s= p_s + TB * OUTC * NETS * DIMK;        // 8*300
    float*  prob_s = logit_s + TB * OUTC * NETS;           // 8*300

    const int tid  = threadIdx.x;
    const int w    = tid >> 5;
    const int o    = w >> 1;
    const int wsub = w & 1;
    const int lane = tid & 31;
    const int k    = lane & 15;
    const int half = lane >> 4;
    const int b0   = blockIdx.x * TB;

    for (int i = tid; i < 4 * H1C; i += RTHREADS) {
        int b = i / H1C;
        int r = i - b * H1C;
        float lo = g_u[(size_t)(b0 + b) * H1C + r];
        float hi = g_u[(size_t)(b0 + b + 4) * H1C + r];
        u2_s[i] = make_float2(lo, hi);
    }
    __syncthreads();

#pragma unroll 1
    for (int ni = 0; ni < 8; ni++) {
        const int nbase = 4 * ni + 2 * wsub;
        if (nbase >= NETS) continue;
        const int n = nbase + half;
        const float* rw = RW + ((size_t)(o * NETS + n) * NODES) * DIMK + k;
        ull rwp[NODES];
#pragma unroll
        for (int d = 0; d < NODES; d++) {
            float r = __ldg(rw + d * DIMK);
            rwp[d] = pack2(r, r);
        }
        const int pidx = o * (NETS * DIMK) + n * DIMK + k;
#pragma unroll
        for (int bp = 0; bp < 4; bp++) {
            const ull* up = (const ull*)(u2_s + bp * H1C + n * NODES);
            ull acc = 0ull;
#pragma unroll
            for (int d = 0; d < NODES; d += 2) {
                ulonglong2 uu = *(const ulonglong2*)(up + d);
                fma2(acc, uu.x, rwp[d]);
                fma2(acc, uu.y, rwp[d + 1]);
            }
            float plo, phi;
            unpack2(acc, plo, phi);
            p_s[bp * (OUTC * NETS * DIMK) + pidx]       = plo;
            p_s[(bp + 4) * (OUTC * NETS * DIMK) + pidx] = phi;
        }
    }
    __syncthreads();

    float v[4];
#pragma unroll 1
    for (int it = 0; it < 3; it++) {
#pragma unroll
        for (int j = 0; j < 4; j++) {
            const int b = wsub * 4 + j;
            const float* pb  = p_s + b * (OUTC * NETS * DIMK) + o * (NETS * DIMK) + k;
            const float* prb = prob_s + b * (OUTC * NETS) + o * NETS;
            float s = 0.f;
            if (it == 0) {
#pragma unroll
                for (int ni = 0; ni < NETS / 2; ni++)
                    s += pb[(2 * ni + half) * DIMK];
                s *= 0.1f;
            } else {
#pragma unroll
                for (int ni = 0; ni < NETS / 2; ni++) {
                    const int n = 2 * ni + half;
                    s = fmaf(prb[n], pb[n * DIMK], s);
                }
            }
            s += __shfl_xor_sync(0xffffffffu, s, 16);
            float sq = s * s;
            sq += __shfl_xor_sync(0xffffffffu, sq, 1);
            sq += __shfl_xor_sync(0xffffffffu, sq, 2);
            sq += __shfl_xor_sync(0xffffffffu, sq, 4);
            sq += __shfl_xor_sync(0xffffffffu, sq, 8);
            v[j] = s * (sq / (1.f + sq)) * rsqrtf(sq);
        }

        if (it < 2) {
#pragma unroll
            for (int j = 0; j < 4; j++) {
                const int b = wsub * 4 + j;
                const float* pb = p_s + b * (OUTC * NETS * DIMK) + o * (NETS * DIMK) + k;
                float* lg = logit_s + b * (OUTC * NETS) + o * NETS;
#pragma unroll
                for (int ni = 0; ni < NETS / 2; ni++) {
                    const int n = 2 * ni + half;
                    float t = pb[n * DIMK] * v[j];
                    t += __shfl_xor_sync(0xffffffffu, t, 1);
                    t += __shfl_xor_sync(0xffffffffu, t, 2);
                    t += __shfl_xor_sync(0xffffffffu, t, 4);
                    t += __shfl_xor_sync(0xffffffffu, t, 8);
                    if (k == 0) lg[n] = (it == 0) ? t : (lg[n] + t);
                }
            }
            __syncthreads();
            for (int t = tid; t < TB * NETS; t += RTHREADS) {
                const int b = t / NETS, n = t - b * NETS;
                const float* lg = logit_s + b * (OUTC * NETS) + n;
                float m = -1e30f;
#pragma unroll
                for (int oo = 0; oo < OUTC; oo++)
                    m = fmaxf(m, lg[oo * NETS]);
                float e[OUTC], ssum = 0.f;
#pragma unroll
                for (int oo = 0; oo < OUTC; oo++) {
                    e[oo] = __expf(lg[oo * NETS] - m);
                    ssum += e[oo];
                }
                float inv = 1.f / ssum;
                float* pr = prob_s + b * (OUTC * NETS) + n;
#pragma unroll
                for (int oo = 0; oo < OUTC; oo++)
                    pr[oo * NETS] = e[oo] * inv;
            }
            __syncthreads();
        }
    }

    if (half == 0) {
#pragma unroll
        for (int j = 0; j < 4; j++)
            out[((size_t)(b0 + wsub * 4 + j) * OUTC + o) * DIMK + k] = v[j];
    }
}

// ---------------- launcher -------------------------------------------------
extern "C" void kernel_launch(void* const* d_in, const int* in_sizes, int n_in,
                              void* d_out, int out_size) {
    const float* x  = (const float*)d_in[0];
    const float* W1 = (const float*)d_in[1];
    const float* b1 = (const float*)d_in[2];
    const float* W2 = (const float*)d_in[3];
    const float* b2 = (const float*)d_in[4];
    const float* RW = (const float*)d_in[5];
    float* out = (float*)d_out;

    static const size_t smem_h2u   = (size_t)(NETS * NODES * NODES + NETS * NODES) * 4;
    static const size_t smem_route = (size_t)(2 * 4 * H1C +
                                              TB * OUTC * NETS * DIMK +
                                              2 * TB * OUTC * NETS) * 4;
    cudaFuncSetAttribute(k_h2u,   cudaFuncAttributeMaxDynamicSharedMemorySize, (int)smem_h2u);
    cudaFuncSetAttribute(k_route, cudaFuncAttributeMaxDynamicSharedMemorySize, (int)smem_route);

    k_convA<<<2048, 256>>>(x);
    k_convW<<<512, 256>>>(W1);
    dim3 g1(NPAD / GBN, B_SZ / GBM);     // (10, 64)
    k_gemm_tc<<<g1, 256>>>(b1);
    k_h2u<<<1024, 256, smem_h2u>>>(W2, b2);
    k_route<<<B_SZ / TB, RTHREADS, smem_route>>>(RW, out);
}